// round 3
// baseline (speedup 1.0000x reference)
#include <cuda_runtime.h>
#include <cuda_bf16.h>
#include <cuda_pipeline.h>

#define B_SZ 32
#define F_SZ 257
#define T_SZ 3000
#define ROUNDS 4
#define TCH 750                 // t per round
#define TCH2 (TCH / 2)          // 375 float2
#define NSEG 4                  // blocks per batch
#define NBLK (B_SZ * NSEG)      // 128 persistent blocks
#define ROWS_A 65               // segs 0..2
#define ROWS_B 62               // seg 3  (3*65 + 62 = 257)
#define THREADS 256
#define MOMENTUM 0.99f
#define ONE_MINUS_M 0.01f
#define EPS 1e-8f

// max tile = 65*750 floats + 750 inv floats
#define SMEM_BYTES ((ROWS_A * TCH + TCH) * 4)

// Persistent scratch + flags (no allocation allowed)
__device__ float g_part[NBLK * TCH];
__device__ float g_invbuf[B_SZ * TCH];
__device__ int   g_ready[NBLK];
__device__ int   g_scan_done[B_SZ];

// ---------------------------------------------------------------------------
__global__ void ema_init() {
    int i = threadIdx.x;
    if (i < NBLK) g_ready[i] = 0;
    if (i < B_SZ) g_scan_done[i] = 0;
}

// ---------------------------------------------------------------------------
__global__ __launch_bounds__(THREADS, 1)
void ema_fused(const float* __restrict__ mag,
               const float* __restrict__ bias,
               const float* __restrict__ running_mean,
               float* __restrict__ out_norm,
               float* __restrict__ out_mean) {
    extern __shared__ float smem[];
    const int blk = blockIdx.x;
    const int b   = blk >> 2;
    const int seg = blk & 3;
    const int f0  = seg * ROWS_A;
    const int R   = (seg < 3) ? ROWS_A : ROWS_B;
    const int tid = threadIdx.x;

    float*  s_tile  = smem;                 // [R * 750]
    float2* s_tile2 = (float2*)smem;        // [R * 375]
    float*  s_inv   = smem + R * TCH;       // [750]
    __shared__ float s_carry;               // EMA state (scanner block only)

    const float bi = bias[0];
    if (seg == 0 && tid == 0) s_carry = running_mean[0];

    const int nf2 = R * TCH2;               // float2 elements in tile

    for (int r = 0; r < ROUNDS; r++) {
        // ---- load tile: mag[b, f0..f0+R, r*750..(r+1)*750) -> SMEM --------
        const size_t gbase = ((size_t)(b * F_SZ + f0)) * T_SZ + (size_t)r * TCH;
        const float2* src2 = (const float2*)(mag + gbase);   // row stride 1500 f2
        for (int idx = tid; idx < nf2; idx += THREADS) {
            int row = idx / TCH2;
            int c   = idx - row * TCH2;
            __pipeline_memcpy_async(&s_tile2[idx], &src2[row * 1500 + c], 8);
        }
        __pipeline_commit();
        __pipeline_wait_prior(0);
        __syncthreads();

        // ---- per-t partial column sums over this block's rows -------------
        for (int t = tid; t < TCH; t += THREADS) {
            float s = 0.f;
            #pragma unroll 1
            for (int row = 0; row < R; row++) s += s_tile[row * TCH + t];
            g_part[blk * TCH + t] = s;
        }
        __syncthreads();
        if (tid == 0) { __threadfence(); atomicExch(&g_ready[blk], r + 1); }

        // ---- scan: block 4b, warp 0 does batch b's EMA for this t-chunk ---
        if (seg == 0 && tid < 32) {
            if (tid == 0) {
                while (atomicAdd(&g_ready[blk + 1], 0) < r + 1) __nanosleep(64);
                while (atomicAdd(&g_ready[blk + 2], 0) < r + 1) __nanosleep(64);
                while (atomicAdd(&g_ready[blk + 3], 0) < r + 1) __nanosleep(64);
            }
            __syncwarp();
            __threadfence();

            const float* p0 = g_part + (size_t)(blk + 0) * TCH;
            const float* p1 = g_part + (size_t)(blk + 1) * TCH;
            const float* p2 = g_part + (size_t)(blk + 2) * TCH;
            const float* p3 = g_part + (size_t)(blk + 3) * TCH;

            float x[24];
            float A = 1.f, Bc = 0.f;
            const int t0 = tid * 24;
            #pragma unroll
            for (int j = 0; j < 24; j++) {
                int t = t0 + j;
                if (t < TCH) {
                    // own partials are local-block (L1 fine); others need L2 (__ldcg)
                    float s = __ldcg(p0 + t) + __ldcg(p1 + t) +
                              __ldcg(p2 + t) + __ldcg(p3 + t);
                    float fm = s * (1.0f / (float)F_SZ);
                    x[j] = fm;
                    A  *= MOMENTUM;
                    Bc  = MOMENTUM * Bc + ONE_MINUS_M * fm;
                }
            }
            // warp inclusive pair scan: (a2,b2)∘(a1,b1) = (a2*a1, a2*b1+b2)
            #pragma unroll
            for (int off = 1; off < 32; off <<= 1) {
                float a1 = __shfl_up_sync(0xffffffff, A,  off);
                float b1 = __shfl_up_sync(0xffffffff, Bc, off);
                if (tid >= off) { Bc = A * b1 + Bc; A = A * a1; }
            }
            float Ap = __shfl_up_sync(0xffffffff, A,  1);
            float Bp = __shfl_up_sync(0xffffffff, Bc, 1);
            if (tid == 0) { Ap = 1.f; Bp = 0.f; }

            float m = Ap * s_carry + Bp;
            float* invp  = g_invbuf + (size_t)b * TCH;
            float* meanp = out_mean + (size_t)b * T_SZ + (size_t)r * TCH;
            #pragma unroll
            for (int j = 0; j < 24; j++) {
                int t = t0 + j;
                if (t < TCH) {
                    m = MOMENTUM * m + ONE_MINUS_M * x[j];
                    float mwb = m + bi;
                    invp[t]  = 1.0f / (mwb + EPS);
                    meanp[t] = mwb;
                }
            }
            __syncwarp();
            if (tid == 31) s_carry = m;      // t = 749 lives in lane 31
            __syncwarp();
            if (tid == 0) { __threadfence(); atomicExch(&g_scan_done[b], r + 1); }
        }

        // ---- acquire scan result ------------------------------------------
        if (tid == 0) {
            while (atomicAdd(&g_scan_done[b], 0) < r + 1) __nanosleep(64);
        }
        __syncthreads();
        __threadfence();

        // inv -> SMEM (cross-block data: bypass possibly-stale L1)
        for (int t = tid; t < TCH; t += THREADS)
            s_inv[t] = __ldcg(g_invbuf + (size_t)b * TCH + t);
        __syncthreads();

        // ---- normalize tile and stream out --------------------------------
        const float2* iv2 = (const float2*)s_inv;
        float2* dst2 = (float2*)(out_norm + gbase);
        for (int idx = tid; idx < nf2; idx += THREADS) {
            int row = idx / TCH2;
            int c   = idx - row * TCH2;
            float2 v = s_tile2[idx];
            float2 iv = iv2[c];
            v.x *= iv.x; v.y *= iv.y;
            __stcs(&dst2[row * 1500 + c], v);
        }
        __syncthreads();   // tile free for next round
    }
}

// ---------------------------------------------------------------------------
extern "C" void kernel_launch(void* const* d_in, const int* in_sizes, int n_in,
                              void* d_out, int out_size) {
    const float* mag          = (const float*)d_in[0];
    const float* bias         = (const float*)d_in[1];
    const float* running_mean = (const float*)d_in[2];
    float* out = (float*)d_out;

    float* out_norm = out;                                // [B, F, T]
    float* out_mean = out + (size_t)B_SZ * F_SZ * T_SZ;   // [B, 1, T]

    static bool attr_done = false;
    if (!attr_done) {
        cudaFuncSetAttribute(ema_fused,
                             cudaFuncAttributeMaxDynamicSharedMemorySize,
                             SMEM_BYTES);
        attr_done = true;
    }

    ema_init<<<1, 256>>>();
    ema_fused<<<NBLK, THREADS, SMEM_BYTES>>>(mag, bias, running_mean,
                                             out_norm, out_mean);
}

// round 4
// speedup vs baseline: 1.9782x; 1.9782x over previous
#include <cuda_runtime.h>
#include <cuda_bf16.h>

#define B_SZ 32
#define F_SZ 257
#define T_SZ 3000
#define NCHUNK_T 2
#define TCH 1500                 // t per chunk
#define TCH4 (TCH / 4)           // 375 float4 per chunk-row
#define T4_ROW (T_SZ / 4)        // 750 float4 full-row stride
#define NFCH 16                  // F-split chunks
#define FCHUNK 17                // 15*17=255, last chunk has 2
#define MOMENTUM 0.99f
#define ONE_MINUS_M 0.01f
#define EPS 1e-8f

// Scratch (static device globals)
__device__ __align__(16) float g_part[NFCH * B_SZ * TCH];  // per-chunk partials
__device__ __align__(16) float g_inv[B_SZ * TCH];          // per-chunk 1/(m+bias+eps)
__device__ float g_carry[B_SZ];                            // EMA state across chunks

// ---------------------------------------------------------------------------
// k1: partial column sums over F-chunks for one t-chunk.
// grid: (ceil(TCH4/128), NFCH, B), block 128.
// ---------------------------------------------------------------------------
__global__ void ema_k1_colsum(const float* __restrict__ mag, int tbase) {
    int t4 = blockIdx.x * blockDim.x + threadIdx.x;
    if (t4 >= TCH4) return;
    int ch = blockIdx.y;
    int b  = blockIdx.z;

    int f0 = ch * FCHUNK;
    int f1 = f0 + FCHUNK;
    if (f1 > F_SZ) f1 = F_SZ;

    const float4* base =
        reinterpret_cast<const float4*>(mag + (size_t)b * F_SZ * T_SZ + tbase) + t4;

    float4 s = make_float4(0.f, 0.f, 0.f, 0.f);
    int f = f0;
    #pragma unroll 1
    for (; f + 8 <= f1; f += 8) {
        float4 v0 = base[(size_t)(f + 0) * T4_ROW];
        float4 v1 = base[(size_t)(f + 1) * T4_ROW];
        float4 v2 = base[(size_t)(f + 2) * T4_ROW];
        float4 v3 = base[(size_t)(f + 3) * T4_ROW];
        float4 v4 = base[(size_t)(f + 4) * T4_ROW];
        float4 v5 = base[(size_t)(f + 5) * T4_ROW];
        float4 v6 = base[(size_t)(f + 6) * T4_ROW];
        float4 v7 = base[(size_t)(f + 7) * T4_ROW];
        s.x += ((v0.x + v1.x) + (v2.x + v3.x)) + ((v4.x + v5.x) + (v6.x + v7.x));
        s.y += ((v0.y + v1.y) + (v2.y + v3.y)) + ((v4.y + v5.y) + (v6.y + v7.y));
        s.z += ((v0.z + v1.z) + (v2.z + v3.z)) + ((v4.z + v5.z) + (v6.z + v7.z));
        s.w += ((v0.w + v1.w) + (v2.w + v3.w)) + ((v4.w + v5.w) + (v6.w + v7.w));
    }
    for (; f < f1; f++) {
        float4 v = base[(size_t)f * T4_ROW];
        s.x += v.x; s.y += v.y; s.z += v.z; s.w += v.w;
    }
    reinterpret_cast<float4*>(g_part)[((size_t)ch * B_SZ + b) * TCH4 + t4] = s;
}

// ---------------------------------------------------------------------------
// k2: per-batch EMA scan of one 1500-step t-chunk; carry via g_carry.
// grid: B blocks of 256 threads; SEG=6 (256*6=1536 >= 1500).
// ---------------------------------------------------------------------------
#define SCAN_THREADS 256
#define SEG 6
__global__ void ema_k2_scan(const float* __restrict__ bias,
                            const float* __restrict__ running_mean,
                            float* __restrict__ out_mean,
                            int chunk) {
    int b   = blockIdx.x;
    int tid = threadIdx.x;
    int t0  = tid * SEG;

    float x[SEG];
    float A = 1.0f, Bacc = 0.0f;

    #pragma unroll
    for (int j = 0; j < SEG; j++) {
        int t = t0 + j;
        if (t < TCH) {
            float s = 0.0f;
            #pragma unroll
            for (int c = 0; c < NFCH; c++)
                s += g_part[((size_t)c * B_SZ + b) * TCH + t];
            float fm = s * (1.0f / (float)F_SZ);
            x[j] = fm;
            A    = MOMENTUM * A;
            Bacc = MOMENTUM * Bacc + ONE_MINUS_M * fm;
        }
    }

    __shared__ float sA[SCAN_THREADS], sB[SCAN_THREADS];
    sA[tid] = A; sB[tid] = Bacc;
    __syncthreads();
    #pragma unroll
    for (int off = 1; off < SCAN_THREADS; off <<= 1) {
        float a2 = sA[tid], b2 = sB[tid];
        float a1 = 1.0f, b1 = 0.0f;
        if (tid >= off) { a1 = sA[tid - off]; b1 = sB[tid - off]; }
        __syncthreads();
        sA[tid] = a2 * a1;
        sB[tid] = a2 * b1 + b2;
        __syncthreads();
    }

    float Ap = 1.0f, Bp = 0.0f;
    if (tid > 0) { Ap = sA[tid - 1]; Bp = sB[tid - 1]; }

    float init = (chunk == 0) ? running_mean[0] : g_carry[b];
    float m  = Ap * init + Bp;
    float bi = bias[0];

    float* invp  = g_inv + (size_t)b * TCH;
    float* meanp = out_mean + (size_t)b * T_SZ + (size_t)chunk * TCH;

    #pragma unroll
    for (int j = 0; j < SEG; j++) {
        int t = t0 + j;
        if (t < TCH) {
            m = MOMENTUM * m + ONE_MINUS_M * x[j];
            float mwb = m + bi;
            invp[t]  = 1.0f / (mwb + EPS);
            meanp[t] = mwb;
            if (t == TCH - 1) g_carry[b] = m;   // state for next chunk
        }
    }
}

// ---------------------------------------------------------------------------
// k3: mag_norm = mag * inv for one t-chunk (mag should be L2-resident).
// grid: (2, F, B), block 256 (512 threads cover 375 float4).
// ---------------------------------------------------------------------------
__global__ void ema_k3_norm(const float* __restrict__ mag,
                            float* __restrict__ out_norm,
                            int tbase) {
    int t4 = blockIdx.x * blockDim.x + threadIdx.x;
    if (t4 >= TCH4) return;
    int f = blockIdx.y;
    int b = blockIdx.z;

    size_t row = ((size_t)b * F_SZ + f) * T_SZ + tbase;
    const float4* src = reinterpret_cast<const float4*>(mag + row) + t4;
    float4*       dst = reinterpret_cast<float4*>(out_norm + row) + t4;

    float4 v  = *src;
    float4 iv = __ldca(reinterpret_cast<const float4*>(g_inv) + (size_t)b * TCH4 + t4);
    v.x *= iv.x; v.y *= iv.y; v.z *= iv.z; v.w *= iv.w;
    __stcs(dst, v);
}

// ---------------------------------------------------------------------------
extern "C" void kernel_launch(void* const* d_in, const int* in_sizes, int n_in,
                              void* d_out, int out_size) {
    const float* mag          = (const float*)d_in[0];
    const float* bias         = (const float*)d_in[1];
    const float* running_mean = (const float*)d_in[2];
    float* out = (float*)d_out;

    float* out_norm = out;                                // [B, F, T]
    float* out_mean = out + (size_t)B_SZ * F_SZ * T_SZ;   // [B, 1, T]

    for (int c = 0; c < NCHUNK_T; c++) {
        int tbase = c * TCH;
        {
            dim3 grid((TCH4 + 127) / 128, NFCH, B_SZ);
            ema_k1_colsum<<<grid, 128>>>(mag, tbase);
        }
        ema_k2_scan<<<B_SZ, SCAN_THREADS>>>(bias, running_mean, out_mean, c);
        {
            dim3 grid((TCH4 + 255) / 256, F_SZ, B_SZ);
            ema_k3_norm<<<grid, 256>>>(mag, out_norm, tbase);
        }
    }
}